// round 11
// baseline (speedup 1.0000x reference)
#include <cuda_runtime.h>
#include <cuda_bf16.h>

// NeuMIP v1, round 11: dual-port weights (4 LDC.128 + 4 LDS.128 per row)
// + texture gathers via ld.global.cg (L1 bypass -> L2 direct), so L1 carries
// ONLY the uniform weight broadcasts. All four resources (LDC port, L1, FMA
// pipe, issue) balanced at ~270K cyc/SM.

#define RESOL 512
#define RMASK 511
#define HID 32
#define NSLOPE 0.01f
#define THREADS 256

typedef unsigned long long ull;

// Constant image: low 16 neurons of each transposed row, packed pairs,
// plus all biases and head weights.
struct __align__(16) CWL {
    ull ow0L[10][8];  ull ow1L[32][8];  ull ow2L[32][8];
    ull rw0L[12][8];  ull rw1L[32][8];  ull rw2L[32][8];
    ull ob0[16]; ull ob1[16]; ull ob2[16];
    ull rb0[16]; ull rb1[16]; ull rb2[16];
    ull ow3[16];          // [32] floats
    ull rw3[3][16];       // [3][32] floats
    float ob3; float rb3[3];
};

__constant__ CWL cw;
__device__ CWL g_stage;

// Shared image: high 16 neurons of each transposed row: [K][16] floats.
struct __align__(16) SWH {
    float ow0H[10 * 16];
    float ow1H[32 * 16];
    float ow2H[32 * 16];
    float rw0H[12 * 16];
    float rw1H[32 * 16];
    float rw2H[32 * 16];
};

__device__ __forceinline__ float leaky(float x) {
    return fmaxf(x, NSLOPE * x);  // slope < 1
}

__device__ __forceinline__ ull fma2(ull a, ull b, ull c) {
    ull d;
    asm("fma.rn.f32x2 %0, %1, %2, %3;" : "=l"(d) : "l"(a), "l"(b), "l"(c));
    return d;
}

__device__ __forceinline__ ull pack2(float lo, float hi) {
    ull d;
    asm("mov.b64 %0, {%1, %2};" : "=l"(d) : "f"(lo), "f"(hi));
    return d;
}

__device__ __forceinline__ void unpack2(ull v, float& lo, float& hi) {
    asm("mov.b64 {%0, %1}, %2;" : "=f"(lo), "=f"(hi) : "l"(v));
}

// L2-direct (L1 bypass) 16-byte load — keeps texture traffic off L1.
__device__ __forceinline__ float4 ldcg4(const float4* p) {
    float4 v;
    asm("ld.global.cg.v4.f32 {%0, %1, %2, %3}, [%4];"
        : "=f"(v.x), "=f"(v.y), "=f"(v.z), "=f"(v.w) : "l"(p));
    return v;
}

// ---------------- prep kernel: build constant staging ----------------

// low 16 neurons, transposed+packed: dstf[i*16 + j] = src[j*K + i], j<16
__device__ __forceinline__ void d_tpose_lo(float* dstf, const float* src,
                                           int K, int tid, int nt) {
    for (int idx = tid; idx < K * 16; idx += nt) {
        int i = idx / 16, j = idx - i * 16;
        dstf[idx] = src[j * K + i];
    }
}

__device__ __forceinline__ void d_copy(float* dst, const float* src, int n,
                                       int tid, int nt) {
    for (int i = tid; i < n; i += nt) dst[i] = src[i];
}

__global__ void prep_kernel(const float* ow0, const float* ob0,
                            const float* ow1, const float* ob1,
                            const float* ow2, const float* ob2,
                            const float* ow3, const float* ob3,
                            const float* rw0, const float* rb0,
                            const float* rw1, const float* rb1,
                            const float* rw2, const float* rb2,
                            const float* rw3, const float* rb3) {
    const int tid = threadIdx.x, nt = blockDim.x;
    d_tpose_lo((float*)g_stage.ow0L, ow0, 10, tid, nt);
    d_tpose_lo((float*)g_stage.ow1L, ow1, 32, tid, nt);
    d_tpose_lo((float*)g_stage.ow2L, ow2, 32, tid, nt);
    d_tpose_lo((float*)g_stage.rw0L, rw0, 12, tid, nt);
    d_tpose_lo((float*)g_stage.rw1L, rw1, 32, tid, nt);
    d_tpose_lo((float*)g_stage.rw2L, rw2, 32, tid, nt);
    d_copy((float*)g_stage.ob0, ob0, 32, tid, nt);
    d_copy((float*)g_stage.ob1, ob1, 32, tid, nt);
    d_copy((float*)g_stage.ob2, ob2, 32, tid, nt);
    d_copy((float*)g_stage.rb0, rb0, 32, tid, nt);
    d_copy((float*)g_stage.rb1, rb1, 32, tid, nt);
    d_copy((float*)g_stage.rb2, rb2, 32, tid, nt);
    d_copy((float*)g_stage.ow3, ow3, 32, tid, nt);
    d_copy((float*)g_stage.rw3, rw3, 96, tid, nt);
    if (tid == 0) {
        g_stage.ob3 = ob3[0];
        g_stage.rb3[0] = rb3[0];
        g_stage.rb3[1] = rb3[1];
        g_stage.rb3[2] = rb3[2];
    }
}

// ---------------- main kernel ----------------

// high 16 neurons into smem: dst[i*16 + (j-16)] = src[j*K + i], j in [16,32)
__device__ __forceinline__ void tcopy_hi(float* dst, const float* src,
                                         int K, int tid, int nt) {
    for (int idx = tid; idx < K * 16; idx += nt) {
        int i = idx / 16, j16 = idx - i * 16;
        dst[idx] = src[(16 + j16) * K + i];
    }
}

// 8-channel bilinear with wrap, L2-direct loads.
__device__ __forceinline__ void bilin8(const float4* __restrict__ t,
                                       float u, float v, float* __restrict__ o) {
    float px = u * (float)RESOL - 0.5f;
    float py = v * (float)RESOL - 0.5f;
    float fpx = floorf(px), fpy = floorf(py);
    float fx = px - fpx, fy = py - fpy;
    int ix = (int)fpx, iy = (int)fpy;
    int x0 = ix & RMASK, x1 = (ix + 1) & RMASK;
    int y0 = iy & RMASK, y1 = (iy + 1) & RMASK;
    float w00 = (1.0f - fx) * (1.0f - fy);
    float w01 = fx * (1.0f - fy);
    float w10 = (1.0f - fx) * fy;
    float w11 = fx * fy;
    const float4* p00 = t + (size_t)(y0 * RESOL + x0) * 2;
    const float4* p01 = t + (size_t)(y0 * RESOL + x1) * 2;
    const float4* p10 = t + (size_t)(y1 * RESOL + x0) * 2;
    const float4* p11 = t + (size_t)(y1 * RESOL + x1) * 2;
    float4 a00 = ldcg4(p00),     b00 = ldcg4(p00 + 1);
    float4 a01 = ldcg4(p01),     b01 = ldcg4(p01 + 1);
    float4 a10 = ldcg4(p10),     b10 = ldcg4(p10 + 1);
    float4 a11 = ldcg4(p11),     b11 = ldcg4(p11 + 1);
    o[0] = w00 * a00.x + w01 * a01.x + w10 * a10.x + w11 * a11.x;
    o[1] = w00 * a00.y + w01 * a01.y + w10 * a10.y + w11 * a11.y;
    o[2] = w00 * a00.z + w01 * a01.z + w10 * a10.z + w11 * a11.z;
    o[3] = w00 * a00.w + w01 * a01.w + w10 * a10.w + w11 * a11.w;
    o[4] = w00 * b00.x + w01 * b01.x + w10 * b10.x + w11 * b11.x;
    o[5] = w00 * b00.y + w01 * b01.y + w10 * b10.y + w11 * b11.y;
    o[6] = w00 * b00.z + w01 * b01.z + w10 * b10.z + w11 * b11.z;
    o[7] = w00 * b00.w + w01 * b01.w + w10 * b10.w + w11 * b11.w;
}

// One layer, 1 point, all 32 neurons:
//  acc[0..7]  <- neurons 0-15  from __constant__ (LDC port, 4x LDC.128)
//  acc[8..15] <- neurons 16-31 from smem (L1 port, 4x broadcast LDS.128)
template <int K>
__device__ __forceinline__ void layerHY(const ull (*__restrict__ wlo)[8],
                                        const float* __restrict__ whi,
                                        const ull* __restrict__ bias,
                                        const float* __restrict__ in,
                                        float* __restrict__ out) {
    ull acc[16];
#pragma unroll
    for (int k = 0; k < 16; k++) acc[k] = bias[k];
#pragma unroll
    for (int i = 0; i < K; i++) {
        ull a = pack2(in[i], in[i]);
#pragma unroll
        for (int q = 0; q < 8; q++) acc[q] = fma2(a, wlo[i][q], acc[q]);
        const ulonglong2* w2 = reinterpret_cast<const ulonglong2*>(whi + i * 16);
#pragma unroll
        for (int q = 0; q < 4; q++) {
            ulonglong2 w = w2[q];
            acc[8 + 2 * q]     = fma2(a, w.x, acc[8 + 2 * q]);
            acc[8 + 2 * q + 1] = fma2(a, w.y, acc[8 + 2 * q + 1]);
        }
    }
#pragma unroll
    for (int k = 0; k < 16; k++) {
        float x, y;
        unpack2(acc[k], x, y);
        out[2 * k]     = leaky(x);
        out[2 * k + 1] = leaky(y);
    }
}

__device__ __forceinline__ float dotC(const ull* __restrict__ w,
                                      const float* __restrict__ v) {
    ull acc = pack2(0.0f, 0.0f);
#pragma unroll
    for (int k = 0; k < 16; k++) {
        acc = fma2(pack2(v[2 * k], v[2 * k + 1]), w[k], acc);
    }
    float lo, hi;
    unpack2(acc, lo, hi);
    return lo + hi;
}

__global__ void __launch_bounds__(THREADS, 3)
neumip_kernel(const float* __restrict__ cam,
              const float* __restrict__ light,
              const float* __restrict__ uv,
              const float* __restrict__ offset_tex,
              const float* __restrict__ rgb_tex,
              const float* __restrict__ ow0, const float* __restrict__ ow1,
              const float* __restrict__ ow2, const float* __restrict__ rw0,
              const float* __restrict__ rw1, const float* __restrict__ rw2,
              float* __restrict__ out, int n) {
    __shared__ SWH s;
    const int tid = threadIdx.x;
    tcopy_hi(s.ow0H, ow0, 10, tid, THREADS);
    tcopy_hi(s.ow1H, ow1, 32, tid, THREADS);
    tcopy_hi(s.ow2H, ow2, 32, tid, THREADS);
    tcopy_hi(s.rw0H, rw0, 12, tid, THREADS);
    tcopy_hi(s.rw1H, rw1, 32, tid, THREADS);
    tcopy_hi(s.rw2H, rw2, 32, tid, THREADS);
    __syncthreads();

    const int p = blockIdx.x * blockDim.x + tid;
    if (p >= n) return;

    const float2 c2 = __ldg(reinterpret_cast<const float2*>(cam) + p);
    const float2 t2 = __ldg(reinterpret_cast<const float2*>(uv) + p);
    const float cx = c2.x, cy = c2.y;
    const float u0 = t2.x, v0 = t2.y;

    // ---- offset texture gather + depth MLP ----
    float in[12];
    bilin8(reinterpret_cast<const float4*>(offset_tex), u0, v0, in);
    in[8] = cx;
    in[9] = cy;

    float ha[HID], hb[HID];
    layerHY<10>(cw.ow0L, s.ow0H, cw.ob0, in, ha);
    layerHY<HID>(cw.ow1L, s.ow1H, cw.ob1, ha, hb);
    layerHY<HID>(cw.ow2L, s.ow2H, cw.ob2, hb, ha);

    float depth = dotC(cw.ow3, ha) + cw.ob3;

    // ---- parallax offset ----
    float z = sqrtf(fmaxf(1.0f - (cx * cx + cy * cy), 1e-6f));
    float sc = depth / z;
    float u1 = u0 + cx * sc;
    float v1 = v0 + cy * sc;

    // ---- rgb texture gather + rgb MLP ----
    const float2 l2 = __ldg(reinterpret_cast<const float2*>(light) + p);
    in[0] = l2.x;
    in[1] = l2.y;
    in[2] = cx;
    in[3] = cy;
    bilin8(reinterpret_cast<const float4*>(rgb_tex), u1, v1, in + 4);

    layerHY<12>(cw.rw0L, s.rw0H, cw.rb0, in, ha);
    layerHY<HID>(cw.rw1L, s.rw1H, cw.rb1, ha, hb);
    layerHY<HID>(cw.rw2L, s.rw2H, cw.rb2, hb, ha);

    out[3 * p + 0] = dotC(cw.rw3[0], ha) + cw.rb3[0];
    out[3 * p + 1] = dotC(cw.rw3[1], ha) + cw.rb3[1];
    out[3 * p + 2] = dotC(cw.rw3[2], ha) + cw.rb3[2];
}

extern "C" void kernel_launch(void* const* d_in, const int* in_sizes, int n_in,
                              void* d_out, int out_size) {
    const float* cam        = (const float*)d_in[0];
    const float* light      = (const float*)d_in[1];
    const float* uv         = (const float*)d_in[2];
    const float* offset_tex = (const float*)d_in[3];
    const float* rgb_tex    = (const float*)d_in[4];

    // 1) pack/transpose low-neuron weight halves + biases into device staging
    prep_kernel<<<1, 256>>>((const float*)d_in[5],  (const float*)d_in[6],
                            (const float*)d_in[7],  (const float*)d_in[8],
                            (const float*)d_in[9],  (const float*)d_in[10],
                            (const float*)d_in[11], (const float*)d_in[12],
                            (const float*)d_in[13], (const float*)d_in[14],
                            (const float*)d_in[15], (const float*)d_in[16],
                            (const float*)d_in[17], (const float*)d_in[18],
                            (const float*)d_in[19], (const float*)d_in[20]);

    // 2) device-to-device copy into the __constant__ image (capturable)
    void* stage_ptr = nullptr;
    cudaGetSymbolAddress(&stage_ptr, g_stage);
    cudaMemcpyToSymbolAsync(cw, stage_ptr, sizeof(CWL), 0,
                            cudaMemcpyDeviceToDevice, 0);

    // 3) main kernel (smem gets the high-neuron halves from global directly)
    const int n = in_sizes[0] / 2;  // camera_dir is (B, 2)
    const int blocks = (n + THREADS - 1) / THREADS;
    neumip_kernel<<<blocks, THREADS>>>(cam, light, uv, offset_tex, rgb_tex,
                                       (const float*)d_in[5],
                                       (const float*)d_in[7],
                                       (const float*)d_in[9],
                                       (const float*)d_in[13],
                                       (const float*)d_in[15],
                                       (const float*)d_in[17],
                                       (float*)d_out, n);
}

// round 13
// speedup vs baseline: 1.1061x; 1.1061x over previous
#include <cuda_runtime.h>
#include <cuda_bf16.h>

// NeuMIP v1, round 13: dual-port weights at LAYER granularity.
//  - depth MLP (ow0,ow1,ow2) + rgb layer0 (rw0): __constant__ (R7-style
//    pure-LDC inner loops, 86 rows -> ~145us on the constant port)
//  - rgb layers 1,2 (rw1,rw2): smem broadcast LDS (R6-style pure loops,
//    64 rows -> ~116us on L1 + ~37us textures = ~153us)
//  - ports overlap ACROSS warps; each inner loop stays single-port
//  - 1 pt/thread, ~80 regs, 24 warps/SM (the zero-excess-stall R7 shape)

#define RESOL 512
#define RMASK 511
#define HID 32
#define NSLOPE 0.01f
#define THREADS 256

typedef unsigned long long ull;

// Constant image: transposed ow0/ow1/ow2/rw0 (packed neuron pairs) + all
// biases + head weights.
struct __align__(16) CWL {
    ulonglong2 ow0T[10 * 8];   // [10][32] floats
    ulonglong2 ow1T[32 * 8];
    ulonglong2 ow2T[32 * 8];
    ulonglong2 rw0T[12 * 8];
    ull ob0[16]; ull ob1[16]; ull ob2[16];
    ull rb0[16]; ull rb1[16]; ull rb2[16];
    ull ow3[16];          // [32] floats
    ull rw3[3][16];       // [3][32] floats
    float ob3; float rb3[3];
};

__constant__ CWL cw;
__device__ CWL g_stage;

// Shared image: transposed rw1/rw2: [K][32] floats.
struct __align__(16) SWS {
    float rw1T[32 * 32];
    float rw2T[32 * 32];
};

__device__ __forceinline__ float leaky(float x) {
    return fmaxf(x, NSLOPE * x);  // slope < 1
}

__device__ __forceinline__ ull fma2(ull a, ull b, ull c) {
    ull d;
    asm("fma.rn.f32x2 %0, %1, %2, %3;" : "=l"(d) : "l"(a), "l"(b), "l"(c));
    return d;
}

__device__ __forceinline__ ull pack2(float lo, float hi) {
    ull d;
    asm("mov.b64 %0, {%1, %2};" : "=l"(d) : "f"(lo), "f"(hi));
    return d;
}

__device__ __forceinline__ void unpack2(ull v, float& lo, float& hi) {
    asm("mov.b64 {%0, %1}, %2;" : "=f"(lo), "=f"(hi) : "l"(v));
}

// ---------------- prep kernel: build constant staging ----------------

// transposed+packed: dstf[i*32 + j] = src[j*K + i]
__device__ __forceinline__ void d_tpose(float* dstf, const float* src,
                                        int K, int tid, int nt) {
    for (int idx = tid; idx < K * 32; idx += nt) {
        int i = idx / 32, j = idx - i * 32;
        dstf[idx] = src[j * K + i];
    }
}

__device__ __forceinline__ void d_copy(float* dst, const float* src, int n,
                                       int tid, int nt) {
    for (int i = tid; i < n; i += nt) dst[i] = src[i];
}

__global__ void prep_kernel(const float* ow0, const float* ob0,
                            const float* ow1, const float* ob1,
                            const float* ow2, const float* ob2,
                            const float* ow3, const float* ob3,
                            const float* rw0, const float* rb0,
                            const float* rw1, const float* rb1,
                            const float* rw2, const float* rb2,
                            const float* rw3, const float* rb3) {
    const int tid = threadIdx.x, nt = blockDim.x;
    d_tpose((float*)g_stage.ow0T, ow0, 10, tid, nt);
    d_tpose((float*)g_stage.ow1T, ow1, 32, tid, nt);
    d_tpose((float*)g_stage.ow2T, ow2, 32, tid, nt);
    d_tpose((float*)g_stage.rw0T, rw0, 12, tid, nt);
    d_copy((float*)g_stage.ob0, ob0, 32, tid, nt);
    d_copy((float*)g_stage.ob1, ob1, 32, tid, nt);
    d_copy((float*)g_stage.ob2, ob2, 32, tid, nt);
    d_copy((float*)g_stage.rb0, rb0, 32, tid, nt);
    d_copy((float*)g_stage.rb1, rb1, 32, tid, nt);
    d_copy((float*)g_stage.rb2, rb2, 32, tid, nt);
    d_copy((float*)g_stage.ow3, ow3, 32, tid, nt);
    d_copy((float*)g_stage.rw3, rw3, 96, tid, nt);
    if (tid == 0) {
        g_stage.ob3 = ob3[0];
        g_stage.rb3[0] = rb3[0];
        g_stage.rb3[1] = rb3[1];
        g_stage.rb3[2] = rb3[2];
    }
}

// ---------------- main kernel ----------------

// transposed into smem: dst[i*32 + j] = src[j*32 + i]  (K = 32)
__device__ __forceinline__ void tcopy32(float* dst, const float* src,
                                        int tid, int nt) {
    for (int idx = tid; idx < 32 * 32; idx += nt) {
        int i = idx >> 5, j = idx & 31;
        dst[idx] = src[j * 32 + i];
    }
}

// 8-channel bilinear with wrap. Texel = 8 contiguous floats = 2x float4.
__device__ __forceinline__ void bilin8(const float4* __restrict__ t,
                                       float u, float v, float* __restrict__ o) {
    float px = u * (float)RESOL - 0.5f;
    float py = v * (float)RESOL - 0.5f;
    float fpx = floorf(px), fpy = floorf(py);
    float fx = px - fpx, fy = py - fpy;
    int ix = (int)fpx, iy = (int)fpy;
    int x0 = ix & RMASK, x1 = (ix + 1) & RMASK;
    int y0 = iy & RMASK, y1 = (iy + 1) & RMASK;
    float w00 = (1.0f - fx) * (1.0f - fy);
    float w01 = fx * (1.0f - fy);
    float w10 = (1.0f - fx) * fy;
    float w11 = fx * fy;
    const float4* p00 = t + (size_t)(y0 * RESOL + x0) * 2;
    const float4* p01 = t + (size_t)(y0 * RESOL + x1) * 2;
    const float4* p10 = t + (size_t)(y1 * RESOL + x0) * 2;
    const float4* p11 = t + (size_t)(y1 * RESOL + x1) * 2;
    float4 a00 = __ldg(p00),     b00 = __ldg(p00 + 1);
    float4 a01 = __ldg(p01),     b01 = __ldg(p01 + 1);
    float4 a10 = __ldg(p10),     b10 = __ldg(p10 + 1);
    float4 a11 = __ldg(p11),     b11 = __ldg(p11 + 1);
    o[0] = w00 * a00.x + w01 * a01.x + w10 * a10.x + w11 * a11.x;
    o[1] = w00 * a00.y + w01 * a01.y + w10 * a10.y + w11 * a11.y;
    o[2] = w00 * a00.z + w01 * a01.z + w10 * a10.z + w11 * a11.z;
    o[3] = w00 * a00.w + w01 * a01.w + w10 * a10.w + w11 * a11.w;
    o[4] = w00 * b00.x + w01 * b01.x + w10 * b10.x + w11 * b11.x;
    o[5] = w00 * b00.y + w01 * b01.y + w10 * b10.y + w11 * b11.y;
    o[6] = w00 * b00.z + w01 * b01.z + w10 * b10.z + w11 * b11.z;
    o[7] = w00 * b00.w + w01 * b01.w + w10 * b10.w + w11 * b11.w;
}

// Pure-constant layer (R7 style): all 32 neurons, 8 LDC.128 per input row.
template <int K>
__device__ __forceinline__ void layerC(const ulonglong2* __restrict__ wT,
                                       const ull* __restrict__ bias,
                                       const float* __restrict__ in,
                                       float* __restrict__ out) {
    ull acc[16];
#pragma unroll
    for (int k = 0; k < 16; k++) acc[k] = bias[k];
#pragma unroll
    for (int i = 0; i < K; i++) {
        ull a = pack2(in[i], in[i]);
#pragma unroll
        for (int q = 0; q < 8; q++) {
            ulonglong2 w = wT[i * 8 + q];
            acc[2 * q]     = fma2(a, w.x, acc[2 * q]);
            acc[2 * q + 1] = fma2(a, w.y, acc[2 * q + 1]);
        }
    }
#pragma unroll
    for (int k = 0; k < 16; k++) {
        float x, y;
        unpack2(acc[k], x, y);
        out[2 * k]     = leaky(x);
        out[2 * k + 1] = leaky(y);
    }
}

// Pure-smem layer (R6 style): all 32 neurons, 4 warp-uniform LDS.128 per row.
__device__ __forceinline__ void layerS(const float* __restrict__ wT,
                                       const ull* __restrict__ bias,
                                       const float* __restrict__ in,
                                       float* __restrict__ out) {
    ull acc[16];
#pragma unroll
    for (int k = 0; k < 16; k++) acc[k] = bias[k];
#pragma unroll
    for (int i = 0; i < HID; i++) {
        ull a = pack2(in[i], in[i]);
        const ulonglong2* w2 = reinterpret_cast<const ulonglong2*>(wT + i * HID);
#pragma unroll
        for (int q = 0; q < 8; q++) {
            ulonglong2 w = w2[q];
            acc[2 * q]     = fma2(a, w.x, acc[2 * q]);
            acc[2 * q + 1] = fma2(a, w.y, acc[2 * q + 1]);
        }
    }
#pragma unroll
    for (int k = 0; k < 16; k++) {
        float x, y;
        unpack2(acc[k], x, y);
        out[2 * k]     = leaky(x);
        out[2 * k + 1] = leaky(y);
    }
}

__device__ __forceinline__ float dotC(const ull* __restrict__ w,
                                      const float* __restrict__ v) {
    ull acc = pack2(0.0f, 0.0f);
#pragma unroll
    for (int k = 0; k < 16; k++) {
        acc = fma2(pack2(v[2 * k], v[2 * k + 1]), w[k], acc);
    }
    float lo, hi;
    unpack2(acc, lo, hi);
    return lo + hi;
}

__global__ void __launch_bounds__(THREADS, 3)
neumip_kernel(const float* __restrict__ cam,
              const float* __restrict__ light,
              const float* __restrict__ uv,
              const float* __restrict__ offset_tex,
              const float* __restrict__ rgb_tex,
              const float* __restrict__ rw1, const float* __restrict__ rw2,
              float* __restrict__ out, int n) {
    __shared__ SWS s;
    const int tid = threadIdx.x;
    tcopy32(s.rw1T, rw1, tid, THREADS);
    tcopy32(s.rw2T, rw2, tid, THREADS);
    __syncthreads();

    const int p = blockIdx.x * blockDim.x + tid;
    if (p >= n) return;

    const float2 c2 = __ldg(reinterpret_cast<const float2*>(cam) + p);
    const float2 t2 = __ldg(reinterpret_cast<const float2*>(uv) + p);
    const float cx = c2.x, cy = c2.y;
    const float u0 = t2.x, v0 = t2.y;

    // ---- offset texture gather + depth MLP (constant port) ----
    float in[12];
    bilin8(reinterpret_cast<const float4*>(offset_tex), u0, v0, in);
    in[8] = cx;
    in[9] = cy;

    float ha[HID], hb[HID];
    layerC<10>(cw.ow0T, cw.ob0, in, ha);
    layerC<HID>(cw.ow1T, cw.ob1, ha, hb);
    layerC<HID>(cw.ow2T, cw.ob2, hb, ha);

    float depth = dotC(cw.ow3, ha) + cw.ob3;

    // ---- parallax offset ----
    float z = sqrtf(fmaxf(1.0f - (cx * cx + cy * cy), 1e-6f));
    float sc = depth / z;
    float u1 = u0 + cx * sc;
    float v1 = v0 + cy * sc;

    // ---- rgb texture gather + rgb MLP ----
    const float2 l2 = __ldg(reinterpret_cast<const float2*>(light) + p);
    in[0] = l2.x;
    in[1] = l2.y;
    in[2] = cx;
    in[3] = cy;
    bilin8(reinterpret_cast<const float4*>(rgb_tex), u1, v1, in + 4);

    layerC<12>(cw.rw0T, cw.rb0, in, ha);   // layer0: constant port
    layerS(s.rw1T, cw.rb1, ha, hb);        // layer1: smem port
    layerS(s.rw2T, cw.rb2, hb, ha);        // layer2: smem port

    out[3 * p + 0] = dotC(cw.rw3[0], ha) + cw.rb3[0];
    out[3 * p + 1] = dotC(cw.rw3[1], ha) + cw.rb3[1];
    out[3 * p + 2] = dotC(cw.rw3[2], ha) + cw.rb3[2];
}

extern "C" void kernel_launch(void* const* d_in, const int* in_sizes, int n_in,
                              void* d_out, int out_size) {
    const float* cam        = (const float*)d_in[0];
    const float* light      = (const float*)d_in[1];
    const float* uv         = (const float*)d_in[2];
    const float* offset_tex = (const float*)d_in[3];
    const float* rgb_tex    = (const float*)d_in[4];

    // 1) pack/transpose const-port weights + biases into device staging
    prep_kernel<<<1, 256>>>((const float*)d_in[5],  (const float*)d_in[6],
                            (const float*)d_in[7],  (const float*)d_in[8],
                            (const float*)d_in[9],  (const float*)d_in[10],
                            (const float*)d_in[11], (const float*)d_in[12],
                            (const float*)d_in[13], (const float*)d_in[14],
                            (const float*)d_in[15], (const float*)d_in[16],
                            (const float*)d_in[17], (const float*)d_in[18],
                            (const float*)d_in[19], (const float*)d_in[20]);

    // 2) device-to-device copy into the __constant__ image (capturable)
    void* stage_ptr = nullptr;
    cudaGetSymbolAddress(&stage_ptr, g_stage);
    cudaMemcpyToSymbolAsync(cw, stage_ptr, sizeof(CWL), 0,
                            cudaMemcpyDeviceToDevice, 0);

    // 3) main kernel (smem layers rw1, rw2 transposed from global)
    const int n = in_sizes[0] / 2;  // camera_dir is (B, 2)
    const int blocks = (n + THREADS - 1) / THREADS;
    neumip_kernel<<<blocks, THREADS>>>(cam, light, uv, offset_tex, rgb_tex,
                                       (const float*)d_in[15],
                                       (const float*)d_in[17],
                                       (float*)d_out, n);
}